// round 2
// baseline (speedup 1.0000x reference)
#include <cuda_runtime.h>
#include <cuda_bf16.h>
#include <mma.h>

using namespace nvcuda;

#define NN 150000
#define EE 150000
#define GG 128
#define DD 512
#define LL 5

// ---------------- scratch (device globals; no allocation) ----------------
__device__ float g_h[(size_t)NN * DD];     // node features
__device__ float g_hx[(size_t)NN * DD];    // linear output
__device__ float g_agg[(size_t)NN * DD];   // aggregation buffer (pre-filled + atomics)
__device__ float g_deg[NN];
__device__ float g_norm[EE];
__device__ float g_vn[GG * DD];
__device__ float g_vnacc[GG * DD];
__device__ float g_t[GG * 2 * DD];         // vn MLP hidden
__device__ double g_colsum[DD];
__device__ double g_colsq[DD];
__device__ float g_mu[DD];
__device__ float g_inv[DD];
__device__ float g_vmu[2 * DD];
__device__ float g_vinv[2 * DD];

// ---------------- small kernels ----------------
__global__ void k_init_deg() {
    int i = blockIdx.x * blockDim.x + threadIdx.x;
    if (i < NN) g_deg[i] = 1.0f;
}

__global__ void k_deg(const int* __restrict__ ei) {
    int e = blockIdx.x * blockDim.x + threadIdx.x;
    if (e < EE) atomicAdd(&g_deg[ei[e]], 1.0f);
}

__global__ void k_norm(const int* __restrict__ ei) {
    int e = blockIdx.x * blockDim.x + threadIdx.x;
    if (e < EE) {
        int r = ei[e];
        int c = ei[EE + e];
        g_norm[e] = rsqrtf(g_deg[r]) * rsqrtf(g_deg[c]);
    }
}

__global__ void k_embed(const int* __restrict__ x, const int* __restrict__ nd,
                        const float* __restrict__ te, const float* __restrict__ ae,
                        const float* __restrict__ de) {
    int idx = blockIdx.x * blockDim.x + threadIdx.x; // N*128 float4 slots
    if (idx >= NN * 128) return;
    int n = idx >> 7;
    int q = (idx & 127) * 4;
    int t0 = x[2 * n];
    int a0 = x[2 * n + 1];
    int dp = nd[n]; if (dp > 20) dp = 20;
    float4 v0 = *(const float4*)&te[(size_t)t0 * DD + q];
    float4 v1 = *(const float4*)&ae[(size_t)a0 * DD + q];
    float4 v2 = *(const float4*)&de[(size_t)dp * DD + q];
    float4 o;
    o.x = v0.x + v1.x + v2.x;
    o.y = v0.y + v1.y + v2.y;
    o.z = v0.z + v1.z + v2.z;
    o.w = v0.w + v1.w + v2.w;
    *(float4*)&g_h[(size_t)n * DD + q] = o;
}

__global__ void k_vninit(const float* __restrict__ vnw) {
    int i = blockIdx.x * blockDim.x + threadIdx.x;
    if (i < GG * DD) g_vn[i] = vnw[i & (DD - 1)];
}

__global__ void k_zero() {
    int i = blockIdx.x * blockDim.x + threadIdx.x;
    if (i < GG * DD) g_vnacc[i] = 0.0f;
    if (i < DD) { g_colsum[i] = 0.0; g_colsq[i] = 0.0; }
}

// ---------------- GEMM (3xTF32): hx = (h + vn[batch]) @ W + lb ; agg = relu(hx+cb)/deg --------
#define BM 128
#define BN 128
#define BK 32

// dynamic smem layout (floats):
//   Ah[128][40]   offset 0
//   Al[128][40]   offset 5120
//   Bh[32][136]   offset 10240
//   Bl[32][136]   offset 14592
// epilogue aliases C[64][136] at offset 0
#define SM_AL 5120
#define SM_BH 10240
#define SM_BL 14592
#define SM_TOT (18944 * 4)

__device__ __forceinline__ void split_tf32(float v, float& hi, float& lo) {
    hi = wmma::__float_to_tf32(v);
    lo = wmma::__float_to_tf32(v - hi);
}

__global__ __launch_bounds__(256) void k_gemm(const int* __restrict__ batch,
                                              const float* __restrict__ W,
                                              const float* __restrict__ lb,
                                              const float* __restrict__ cb) {
    extern __shared__ float sm[];
    float (*Ah)[40]  = (float(*)[40])sm;
    float (*Al)[40]  = (float(*)[40])(sm + SM_AL);
    float (*Bh)[136] = (float(*)[136])(sm + SM_BH);
    float (*Bl)[136] = (float(*)[136])(sm + SM_BL);
    float (*C)[136]  = (float(*)[136])sm;

    int rowBase = blockIdx.x * BM;
    int colBase = blockIdx.y * BN;
    int tid = threadIdx.x;
    int warp = tid >> 5;
    int wm = warp >> 2;   // 0..1
    int wn = warp & 3;    // 0..3

    wmma::fragment<wmma::accumulator, 16, 16, 8, float> acc[4][2];
#pragma unroll
    for (int i = 0; i < 4; i++)
#pragma unroll
        for (int j = 0; j < 2; j++) wmma::fill_fragment(acc[i][j], 0.0f);

    for (int k0 = 0; k0 < DD; k0 += BK) {
        // load A tile (128 x 32) with vn fusion, split hi/lo
#pragma unroll
        for (int i = 0; i < 4; i++) {
            int idx = tid + i * 256;      // 0..1023
            int r = idx >> 3;
            int c = (idx & 7) * 4;
            int row = rowBase + r;
            float4 v = make_float4(0.f, 0.f, 0.f, 0.f);
            if (row < NN) {
                v = *(const float4*)&g_h[(size_t)row * DD + k0 + c];
                int bg = batch[row];
                float4 vv = *(const float4*)&g_vn[bg * DD + k0 + c];
                v.x += vv.x; v.y += vv.y; v.z += vv.z; v.w += vv.w;
            }
            float h0, l0, h1, l1, h2, l2, h3, l3;
            split_tf32(v.x, h0, l0); split_tf32(v.y, h1, l1);
            split_tf32(v.z, h2, l2); split_tf32(v.w, h3, l3);
            Ah[r][c + 0] = h0; Ah[r][c + 1] = h1; Ah[r][c + 2] = h2; Ah[r][c + 3] = h3;
            Al[r][c + 0] = l0; Al[r][c + 1] = l1; Al[r][c + 2] = l2; Al[r][c + 3] = l3;
        }
        // load B tile (32 x 128), split hi/lo
#pragma unroll
        for (int i = 0; i < 4; i++) {
            int idx = tid + i * 256;
            int r = idx >> 5;
            int c = (idx & 31) * 4;
            float4 w = *(const float4*)&W[(size_t)(k0 + r) * DD + colBase + c];
            float h0, l0, h1, l1, h2, l2, h3, l3;
            split_tf32(w.x, h0, l0); split_tf32(w.y, h1, l1);
            split_tf32(w.z, h2, l2); split_tf32(w.w, h3, l3);
            Bh[r][c + 0] = h0; Bh[r][c + 1] = h1; Bh[r][c + 2] = h2; Bh[r][c + 3] = h3;
            Bl[r][c + 0] = l0; Bl[r][c + 1] = l1; Bl[r][c + 2] = l2; Bl[r][c + 3] = l3;
        }
        __syncthreads();
#pragma unroll
        for (int kk = 0; kk < BK; kk += 8) {
            wmma::fragment<wmma::matrix_a, 16, 16, 8, wmma::precision::tf32, wmma::row_major> afh[4], afl[4];
            wmma::fragment<wmma::matrix_b, 16, 16, 8, wmma::precision::tf32, wmma::row_major> bfh[2], bfl[2];
#pragma unroll
            for (int i = 0; i < 4; i++) {
                wmma::load_matrix_sync(afh[i], &Ah[wm * 64 + i * 16][kk], 40);
                wmma::load_matrix_sync(afl[i], &Al[wm * 64 + i * 16][kk], 40);
            }
#pragma unroll
            for (int j = 0; j < 2; j++) {
                wmma::load_matrix_sync(bfh[j], &Bh[kk][wn * 32 + j * 16], 136);
                wmma::load_matrix_sync(bfl[j], &Bl[kk][wn * 32 + j * 16], 136);
            }
#pragma unroll
            for (int i = 0; i < 4; i++)
#pragma unroll
                for (int j = 0; j < 2; j++) {
                    wmma::mma_sync(acc[i][j], afh[i], bfl[j], acc[i][j]);
                    wmma::mma_sync(acc[i][j], afl[i], bfh[j], acc[i][j]);
                    wmma::mma_sync(acc[i][j], afh[i], bfh[j], acc[i][j]);
                }
        }
        __syncthreads();
    }

    // epilogue: stage 64 rows at a time through shared, fuse bias + agg init
    for (int half = 0; half < 2; half++) {
        if (wm == half) {
#pragma unroll
            for (int i = 0; i < 4; i++)
#pragma unroll
                for (int j = 0; j < 2; j++)
                    wmma::store_matrix_sync(&C[i * 16][wn * 32 + j * 16], acc[i][j], 136,
                                            wmma::mem_row_major);
        }
        __syncthreads();
#pragma unroll
        for (int i = 0; i < 8; i++) {
            int idx = tid + i * 256;     // 0..2047 (64 rows x 32 float4)
            int r = idx >> 5;
            int c = (idx & 31) * 4;
            int row = rowBase + half * 64 + r;
            if (row < NN) {
                int col = colBase + c;
                float4 v = *(float4*)&C[r][c];
                float4 b4 = *(const float4*)&lb[col];
                v.x += b4.x; v.y += b4.y; v.z += b4.z; v.w += b4.w;
                *(float4*)&g_hx[(size_t)row * DD + col] = v;
                float dg = g_deg[row];
                float4 cb4 = *(const float4*)&cb[col];
                float4 a;
                a.x = fmaxf(v.x + cb4.x, 0.f) / dg;
                a.y = fmaxf(v.y + cb4.y, 0.f) / dg;
                a.z = fmaxf(v.z + cb4.z, 0.f) / dg;
                a.w = fmaxf(v.w + cb4.w, 0.f) / dg;
                *(float4*)&g_agg[(size_t)row * DD + col] = a;
            }
        }
        __syncthreads();
    }
}

// ---------------- message: agg[col] += norm * relu(hx[row] + edge_attr@edge_w + eb) ----------------
__global__ void k_message(const int* __restrict__ ei, const float* __restrict__ ea,
                          const float* __restrict__ ew, const float* __restrict__ eb) {
    int e = blockIdx.x;
    int t = threadIdx.x;       // 0..127
    int d = t * 4;
    int row = ei[e];
    int col = ei[EE + e];
    float nm = g_norm[e];
    float a0 = ea[2 * e];
    float a1 = ea[2 * e + 1];
    float4 w0 = *(const float4*)&ew[d];
    float4 w1 = *(const float4*)&ew[DD + d];
    float4 b4 = *(const float4*)&eb[d];
    float4 h4 = *(const float4*)&g_hx[(size_t)row * DD + d];
    float mx = nm * fmaxf(h4.x + a0 * w0.x + a1 * w1.x + b4.x, 0.f);
    float my = nm * fmaxf(h4.y + a0 * w0.y + a1 * w1.y + b4.y, 0.f);
    float mz = nm * fmaxf(h4.z + a0 * w0.z + a1 * w1.z + b4.z, 0.f);
    float mw = nm * fmaxf(h4.w + a0 * w0.w + a1 * w1.w + b4.w, 0.f);
    float* p = &g_agg[(size_t)col * DD + d];
    asm volatile("red.global.add.v4.f32 [%0], {%1,%2,%3,%4};"
                 :: "l"(p), "f"(mx), "f"(my), "f"(mz), "f"(mw) : "memory");
}

// ---------------- BN stats over columns ----------------
__global__ void k_stats() {
    int c = threadIdx.x;       // 512 threads, column per thread
    int base = blockIdx.x * 256;
    float s = 0.f, s2 = 0.f;
    for (int r = 0; r < 256; r++) {
        int row = base + r;
        if (row >= NN) break;
        float v = g_agg[(size_t)row * DD + c];
        s += v;
        s2 += v * v;
    }
    atomicAdd(&g_colsum[c], (double)s);
    atomicAdd(&g_colsq[c], (double)s2);
}

__global__ void k_finalize() {
    int c = threadIdx.x;
    if (c < DD) {
        double mu = g_colsum[c] / (double)NN;
        double var = g_colsq[c] / (double)NN - mu * mu;
        g_mu[c] = (float)mu;
        g_inv[c] = (float)(1.0 / sqrt(var + 1e-5));
    }
}

// ---------------- BN apply (+relu + vn pooling, or final output) ----------------
__global__ void k_bnapply(const int* __restrict__ batch, const float* __restrict__ ga,
                          const float* __restrict__ be, float* __restrict__ out, int last) {
    int c = threadIdx.x;
    int base = blockIdx.x * 64;
    float mu = g_mu[c], inv = g_inv[c], g = ga[c], b = be[c];
    if (last) {
        for (int r = 0; r < 64; r++) {
            int row = base + r;
            if (row >= NN) break;
            float v = g_agg[(size_t)row * DD + c];
            out[(size_t)row * DD + c] = (v - mu) * inv * g + b;
        }
        return;
    }
    int cur = -1;
    float acc = 0.f;
    for (int r = 0; r < 64; r++) {
        int row = base + r;
        if (row >= NN) break;
        float v = g_agg[(size_t)row * DD + c];
        v = (v - mu) * inv * g + b;
        v = fmaxf(v, 0.f);
        g_h[(size_t)row * DD + c] = v;
        int bg = batch[row];
        if (bg != cur) {
            if (cur >= 0) atomicAdd(&g_vnacc[cur * DD + c], acc);
            cur = bg;
            acc = 0.f;
        }
        acc += v;
    }
    if (cur >= 0) atomicAdd(&g_vnacc[cur * DD + c], acc);
}

// ---------------- virtual-node MLP ----------------
// t = (vn + vnacc) @ W1 + b1      [128, 1024]
__global__ void k_vng1(const float* __restrict__ W1, const float* __restrict__ b1) {
    __shared__ float sh[2][DD];
    int r0 = blockIdx.x * 2;
    int tid = threadIdx.x;       // 256
#pragma unroll
    for (int i = 0; i < 4; i++) {
        int idx = tid + i * 256; // 0..1023
        int r = idx >> 9;
        int c = idx & 511;
        sh[r][c] = g_vn[(r0 + r) * DD + c] + g_vnacc[(r0 + r) * DD + c];
    }
    __syncthreads();
    float acc[2][4] = {{0.f, 0.f, 0.f, 0.f}, {0.f, 0.f, 0.f, 0.f}};
    for (int k = 0; k < DD; k++) {
        float s0 = sh[0][k], s1 = sh[1][k];
#pragma unroll
        for (int j = 0; j < 4; j++) {
            float w = W1[(size_t)k * 1024 + tid + j * 256];
            acc[0][j] += s0 * w;
            acc[1][j] += s1 * w;
        }
    }
#pragma unroll
    for (int r = 0; r < 2; r++)
#pragma unroll
        for (int j = 0; j < 4; j++) {
            int col = tid + j * 256;
            g_t[(r0 + r) * 1024 + col] = acc[r][j] + b1[col];
        }
}

__global__ void k_vnstats() {
    int c = threadIdx.x;   // 1024
    float s = 0.f, s2 = 0.f;
    for (int r = 0; r < GG; r++) {
        float v = g_t[r * 1024 + c];
        s += v; s2 += v * v;
    }
    float mu = s / (float)GG;
    float var = s2 / (float)GG - mu * mu;
    g_vmu[c] = mu;
    g_vinv[c] = rsqrtf(var + 1e-5f);
}

// vn = relu(bn(t)) @ W2 + b2    [128, 512]
__global__ void k_vng2(const float* __restrict__ W2, const float* __restrict__ b2,
                       const float* __restrict__ mg, const float* __restrict__ mbb) {
    __shared__ float sh[2][2 * DD];
    int r0 = blockIdx.x * 2;
    int tid = threadIdx.x;       // 256
#pragma unroll
    for (int i = 0; i < 8; i++) {
        int idx = tid + i * 256; // 0..2047
        int r = idx >> 10;
        int c = idx & 1023;
        float v = g_t[(r0 + r) * 1024 + c];
        v = (v - g_vmu[c]) * g_vinv[c] * mg[c] + mbb[c];
        sh[r][c] = fmaxf(v, 0.f);
    }
    __syncthreads();
    float acc[2][2] = {{0.f, 0.f}, {0.f, 0.f}};
    for (int k = 0; k < 1024; k++) {
        float s0 = sh[0][k], s1 = sh[1][k];
#pragma unroll
        for (int j = 0; j < 2; j++) {
            float w = W2[(size_t)k * DD + tid + j * 256];
            acc[0][j] += s0 * w;
            acc[1][j] += s1 * w;
        }
    }
#pragma unroll
    for (int r = 0; r < 2; r++)
#pragma unroll
        for (int j = 0; j < 2; j++) {
            int col = tid + j * 256;
            g_vn[(r0 + r) * DD + col] = acc[r][j] + b2[col];
        }
}

// ---------------- launcher ----------------
extern "C" void kernel_launch(void* const* d_in, const int* in_sizes, int n_in,
                              void* d_out, int out_size) {
    const int*   x     = (const int*)d_in[0];
    const int*   nd    = (const int*)d_in[1];
    const int*   ei    = (const int*)d_in[2];
    const int*   batch = (const int*)d_in[3];
    const float* ea    = (const float*)d_in[4];
    const float* te    = (const float*)d_in[5];
    const float* ae    = (const float*)d_in[6];
    const float* de    = (const float*)d_in[7];
    const float* vnw   = (const float*)d_in[8];
    const float* lw    = (const float*)d_in[9];
    const float* lb    = (const float*)d_in[10];
    const float* cb    = (const float*)d_in[11];
    const float* ew    = (const float*)d_in[12];
    const float* ebi   = (const float*)d_in[13];
    const float* bng   = (const float*)d_in[14];
    const float* bnb   = (const float*)d_in[15];
    const float* mw1   = (const float*)d_in[16];
    const float* mb1   = (const float*)d_in[17];
    const float* mg    = (const float*)d_in[18];
    const float* mbb   = (const float*)d_in[19];
    const float* mw2   = (const float*)d_in[20];
    const float* mb2   = (const float*)d_in[21];
    float* out = (float*)d_out;

    static int smem_set = 0;
    if (!smem_set) {
        cudaFuncSetAttribute(k_gemm, cudaFuncAttributeMaxDynamicSharedMemorySize, SM_TOT);
        smem_set = 1;
    }

    k_init_deg<<<(NN + 255) / 256, 256>>>();
    k_deg<<<(EE + 255) / 256, 256>>>(ei);
    k_norm<<<(EE + 255) / 256, 256>>>(ei);
    k_embed<<<(NN * 128 + 255) / 256, 256>>>(x, nd, te, ae, de);
    k_vninit<<<(GG * DD + 255) / 256, 256>>>(vnw);

    for (int l = 0; l < LL; l++) {
        int last = (l == LL - 1) ? 1 : 0;
        k_zero<<<(GG * DD + 255) / 256, 256>>>();
        k_gemm<<<dim3((NN + BM - 1) / BM, DD / BN), 256, SM_TOT>>>(
            batch, lw + (size_t)l * DD * DD, lb + l * DD, cb + l * DD);
        k_message<<<EE, 128>>>(ei, ea, ew + (size_t)l * 2 * DD, ebi + l * DD);
        k_stats<<<(NN + 255) / 256, 512>>>();
        k_finalize<<<1, 512>>>();
        k_bnapply<<<(NN + 63) / 64, 512>>>(batch, bng + l * DD, bnb + l * DD, out, last);
        if (!last) {
            k_vng1<<<GG / 2, 256>>>(mw1 + (size_t)l * DD * 2 * DD, mb1 + l * 2 * DD);
            k_vnstats<<<1, 1024>>>();
            k_vng2<<<GG / 2, 256>>>(mw2 + (size_t)l * 2 * DD * DD, mb2 + l * DD,
                                    mg + l * 2 * DD, mbb + l * 2 * DD);
        }
    }
    (void)in_sizes; (void)n_in; (void)out_size;
}

// round 4
// speedup vs baseline: 2.4667x; 2.4667x over previous
#include <cuda_runtime.h>
#include <cuda_bf16.h>
#include <mma.h>
#include <cstdint>

using namespace nvcuda;

#define NN 150000
#define NN2 150016          // padded to 1172*128
#define EE 150000
#define GG 128
#define DD 512
#define LL 5

// ---------------- scratch (device globals; no allocation) ----------------
__device__ float g_h[(size_t)NN * DD];     // node features
__device__ float g_hx[(size_t)NN * DD];    // linear output
__device__ float g_agg[(size_t)NN * DD];   // aggregation buffer (pre-filled + atomics)
__device__ __nv_bfloat16 g_ahi[(size_t)NN2 * DD];  // split A (zero-init covers pad rows)
__device__ __nv_bfloat16 g_alo[(size_t)NN2 * DD];
__device__ __nv_bfloat16 g_whi[DD * DD];
__device__ __nv_bfloat16 g_wlo[DD * DD];
__device__ float g_deg[NN];
__device__ float g_norm[EE];
__device__ float g_vn[GG * DD];
__device__ float g_vnacc[GG * DD];
__device__ float g_t[GG * 2 * DD];         // vn MLP hidden
__device__ double g_colsum[DD];
__device__ double g_colsq[DD];
__device__ float g_mu[DD];
__device__ float g_inv[DD];
__device__ float g_vmu[2 * DD];
__device__ float g_vinv[2 * DD];

// ---------------- small kernels ----------------
__global__ void k_init_deg() {
    int i = blockIdx.x * blockDim.x + threadIdx.x;
    if (i < NN) g_deg[i] = 1.0f;
}

__global__ void k_deg(const int* __restrict__ ei) {
    int e = blockIdx.x * blockDim.x + threadIdx.x;
    if (e < EE) atomicAdd(&g_deg[ei[e]], 1.0f);
}

__global__ void k_norm(const int* __restrict__ ei) {
    int e = blockIdx.x * blockDim.x + threadIdx.x;
    if (e < EE) {
        int r = ei[e];
        int c = ei[EE + e];
        g_norm[e] = rsqrtf(g_deg[r]) * rsqrtf(g_deg[c]);
    }
}

__global__ void k_embed(const int* __restrict__ x, const int* __restrict__ nd,
                        const float* __restrict__ te, const float* __restrict__ ae,
                        const float* __restrict__ de) {
    int idx = blockIdx.x * blockDim.x + threadIdx.x;
    if (idx >= NN * 128) return;
    int n = idx >> 7;
    int q = (idx & 127) * 4;
    int t0 = x[2 * n];
    int a0 = x[2 * n + 1];
    int dp = nd[n]; if (dp > 20) dp = 20;
    float4 v0 = *(const float4*)&te[(size_t)t0 * DD + q];
    float4 v1 = *(const float4*)&ae[(size_t)a0 * DD + q];
    float4 v2 = *(const float4*)&de[(size_t)dp * DD + q];
    float4 o;
    o.x = v0.x + v1.x + v2.x;
    o.y = v0.y + v1.y + v2.y;
    o.z = v0.z + v1.z + v2.z;
    o.w = v0.w + v1.w + v2.w;
    *(float4*)&g_h[(size_t)n * DD + q] = o;
}

__global__ void k_vninit(const float* __restrict__ vnw) {
    int i = blockIdx.x * blockDim.x + threadIdx.x;
    if (i < GG * DD) g_vn[i] = vnw[i & (DD - 1)];
}

__global__ void k_zero() {
    int i = blockIdx.x * blockDim.x + threadIdx.x;
    if (i < GG * DD) g_vnacc[i] = 0.0f;
    if (i < DD) { g_colsum[i] = 0.0; g_colsq[i] = 0.0; }
}

// ---------------- split kernels (bf16 hi/lo) ----------------
__device__ __forceinline__ void bsplit(float a, __nv_bfloat16& hi, __nv_bfloat16& lo) {
    hi = __float2bfloat16(a);
    lo = __float2bfloat16(a - __bfloat162float(hi));
}

__global__ void k_split_a(const int* __restrict__ batch) {
    int idx = blockIdx.x * blockDim.x + threadIdx.x;
    if (idx >= NN * 128) return;
    int n = idx >> 7;
    int q = (idx & 127) * 4;
    float4 v = *(const float4*)&g_h[(size_t)n * DD + q];
    int bg = batch[n];
    float4 w = *(const float4*)&g_vn[bg * DD + q];
    float a0 = v.x + w.x, a1 = v.y + w.y, a2 = v.z + w.z, a3 = v.w + w.w;
    __nv_bfloat16 h0, l0, h1, l1, h2, l2, h3, l3;
    bsplit(a0, h0, l0); bsplit(a1, h1, l1); bsplit(a2, h2, l2); bsplit(a3, h3, l3);
    size_t off = (size_t)n * DD + q;
    *(__nv_bfloat162*)&g_ahi[off] = __nv_bfloat162(h0, h1);
    *(__nv_bfloat162*)&g_ahi[off + 2] = __nv_bfloat162(h2, h3);
    *(__nv_bfloat162*)&g_alo[off] = __nv_bfloat162(l0, l1);
    *(__nv_bfloat162*)&g_alo[off + 2] = __nv_bfloat162(l2, l3);
}

__global__ void k_split_w(const float* __restrict__ W) {
    int idx = blockIdx.x * blockDim.x + threadIdx.x;   // 65536
    if (idx >= DD * DD / 4) return;
    int q = idx * 4;
    float4 v = *(const float4*)&W[q];
    __nv_bfloat16 h0, l0, h1, l1, h2, l2, h3, l3;
    bsplit(v.x, h0, l0); bsplit(v.y, h1, l1); bsplit(v.z, h2, l2); bsplit(v.w, h3, l3);
    *(__nv_bfloat162*)&g_whi[q] = __nv_bfloat162(h0, h1);
    *(__nv_bfloat162*)&g_whi[q + 2] = __nv_bfloat162(h2, h3);
    *(__nv_bfloat162*)&g_wlo[q] = __nv_bfloat162(l0, l1);
    *(__nv_bfloat162*)&g_wlo[q + 2] = __nv_bfloat162(l2, l3);
}

// ---------------- GEMM (bf16x3, cp.async double-buffered) ----------------
// hx = A @ W + lb ; agg = relu(hx+cb)/deg,  A = h + vn[batch] (presplit)
#define BM 128
#define BN 128
#define BK 32

// smem stage layout (bytes):
//   Ah [128][40] bf16 : 0      (10240)
//   Al [128][40] bf16 : 10240  (10240)
//   Bh [32][136] bf16 : 20480  (8704)
//   Bl [32][136] bf16 : 29184  (8704)
#define STG 37888
#define OAL 10240
#define OBH 20480
#define OBL 29184
#define SM_TOT (2 * STG)

__device__ __forceinline__ void cpa16(uint32_t dst, const void* src) {
    asm volatile("cp.async.cg.shared.global [%0], [%1], 16;\n" :: "r"(dst), "l"(src));
}
__device__ __forceinline__ void cpa8(uint32_t dst, const void* src) {
    asm volatile("cp.async.ca.shared.global [%0], [%1], 8;\n" :: "r"(dst), "l"(src));
}
__device__ __forceinline__ void cp_commit() {
    asm volatile("cp.async.commit_group;\n");
}
template<int Nw> __device__ __forceinline__ void cp_wait() {
    asm volatile("cp.async.wait_group %0;\n" :: "n"(Nw));
}

__global__ __launch_bounds__(256, 2) void k_gemm(const float* __restrict__ lb,
                                                 const float* __restrict__ cb) {
    extern __shared__ char smc[];
    uint32_t sbase = (uint32_t)__cvta_generic_to_shared(smc);
    int tid = threadIdx.x;
    int warp = tid >> 5;
    int wm = warp >> 2;   // 0..1
    int wn = warp & 3;    // 0..3
    int nBase = blockIdx.x * BN;   // column block (x fastest -> A tile L2 reuse)
    int mBase = blockIdx.y * BM;

    wmma::fragment<wmma::accumulator, 16, 16, 16, float> acc[4][2];
#pragma unroll
    for (int i = 0; i < 4; i++)
#pragma unroll
        for (int j = 0; j < 2; j++) wmma::fill_fragment(acc[i][j], 0.0f);

    auto loadStage = [&](int s, int k0) {
        uint32_t base = sbase + s * STG;
        // A hi/lo: 2048 chunks of 8B
#pragma unroll
        for (int i = 0; i < 8; i++) {
            int idx = tid + i * 256;
            int half = idx >> 10;
            int rem = idx & 1023;
            int r = rem >> 3;
            int c = rem & 7;
            const __nv_bfloat16* src =
                (half ? g_alo : g_ahi) + (size_t)(mBase + r) * DD + k0 + c * 4;
            cpa8(base + half * OAL + r * 80 + c * 8, src);
        }
        // B hi/lo: 1024 chunks of 16B
#pragma unroll
        for (int i = 0; i < 4; i++) {
            int idx = tid + i * 256;
            int half = idx >> 9;
            int rem = idx & 511;
            int r = rem >> 4;
            int c = rem & 15;
            const __nv_bfloat16* src =
                (half ? g_wlo : g_whi) + (size_t)(k0 + r) * DD + nBase + c * 8;
            cpa16(base + OBH + half * 8704 + r * 272 + c * 16, src);
        }
    };

    loadStage(0, 0);
    cp_commit();

    for (int it = 0; it < DD / BK; it++) {
        if (it < DD / BK - 1) {
            loadStage((it + 1) & 1, (it + 1) * BK);
            cp_commit();
            cp_wait<1>();
        } else {
            cp_wait<0>();
        }
        __syncthreads();
        char* st = smc + (it & 1) * STG;
        const __nv_bfloat16* Ah = (const __nv_bfloat16*)st;
        const __nv_bfloat16* Al = (const __nv_bfloat16*)(st + OAL);
        const __nv_bfloat16* Bh = (const __nv_bfloat16*)(st + OBH);
        const __nv_bfloat16* Bl = (const __nv_bfloat16*)(st + OBL);
#pragma unroll
        for (int kk = 0; kk < BK; kk += 16) {
            wmma::fragment<wmma::matrix_a, 16, 16, 16, __nv_bfloat16, wmma::row_major> ah[4], al[4];
            wmma::fragment<wmma::matrix_b, 16, 16, 16, __nv_bfloat16, wmma::row_major> bh[2], bl[2];
#pragma unroll
            for (int i = 0; i < 4; i++) {
                wmma::load_matrix_sync(ah[i], Ah + (wm * 64 + i * 16) * 40 + kk, 40);
                wmma::load_matrix_sync(al[i], Al + (wm * 64 + i * 16) * 40 + kk, 40);
            }
#pragma unroll
            for (int j = 0; j < 2; j++) {
                wmma::load_matrix_sync(bh[j], Bh + kk * 136 + wn * 32 + j * 16, 136);
                wmma::load_matrix_sync(bl[j], Bl + kk * 136 + wn * 32 + j * 16, 136);
            }
#pragma unroll
            for (int i = 0; i < 4; i++)
#pragma unroll
                for (int j = 0; j < 2; j++) {
                    wmma::mma_sync(acc[i][j], ah[i], bl[j], acc[i][j]);
                    wmma::mma_sync(acc[i][j], al[i], bh[j], acc[i][j]);
                    wmma::mma_sync(acc[i][j], ah[i], bh[j], acc[i][j]);
                }
        }
        __syncthreads();
    }

    // epilogue: stage 64 rows at a time through shared, fuse bias + agg init
    float (*C)[136] = (float(*)[136])smc;
    for (int half = 0; half < 2; half++) {
        if (wm == half) {
#pragma unroll
            for (int i = 0; i < 4; i++)
#pragma unroll
                for (int j = 0; j < 2; j++)
                    wmma::store_matrix_sync(&C[i * 16][wn * 32 + j * 16], acc[i][j], 136,
                                            wmma::mem_row_major);
        }
        __syncthreads();
#pragma unroll
        for (int i = 0; i < 8; i++) {
            int idx = tid + i * 256;     // 0..2047 (64 rows x 32 float4)
            int r = idx >> 5;
            int c = (idx & 31) * 4;
            int row = mBase + half * 64 + r;
            if (row < NN) {
                int col = nBase + c;
                float4 v = *(float4*)&C[r][c];
                float4 b4 = *(const float4*)&lb[col];
                v.x += b4.x; v.y += b4.y; v.z += b4.z; v.w += b4.w;
                *(float4*)&g_hx[(size_t)row * DD + col] = v;
                float dg = g_deg[row];
                float4 cb4 = *(const float4*)&cb[col];
                float4 a;
                a.x = fmaxf(v.x + cb4.x, 0.f) / dg;
                a.y = fmaxf(v.y + cb4.y, 0.f) / dg;
                a.z = fmaxf(v.z + cb4.z, 0.f) / dg;
                a.w = fmaxf(v.w + cb4.w, 0.f) / dg;
                *(float4*)&g_agg[(size_t)row * DD + col] = a;
            }
        }
        __syncthreads();
    }
}

// ---------------- message: agg[col] += norm * relu(hx[row] + edge_attr@edge_w + eb) ----------------
__global__ void k_message(const int* __restrict__ ei, const float* __restrict__ ea,
                          const float* __restrict__ ew, const float* __restrict__ eb) {
    int e = blockIdx.x;
    int t = threadIdx.x;       // 0..127
    int d = t * 4;
    int row = ei[e];
    int col = ei[EE + e];
    float nm = g_norm[e];
    float a0 = ea[2 * e];
    float a1 = ea[2 * e + 1];
    float4 w0 = *(const float4*)&ew[d];
    float4 w1 = *(const float4*)&ew[DD + d];
    float4 b4 = *(const float4*)&eb[d];
    float4 h4 = *(const float4*)&g_hx[(size_t)row * DD + d];
    float mx = nm * fmaxf(h4.x + a0 * w0.x + a1 * w1.x + b4.x, 0.f);
    float my = nm * fmaxf(h4.y + a0 * w0.y + a1 * w1.y + b4.y, 0.f);
    float mz = nm * fmaxf(h4.z + a0 * w0.z + a1 * w1.z + b4.z, 0.f);
    float mw = nm * fmaxf(h4.w + a0 * w0.w + a1 * w1.w + b4.w, 0.f);
    float* p = &g_agg[(size_t)col * DD + d];
    asm volatile("red.global.add.v4.f32 [%0], {%1,%2,%3,%4};"
                 :: "l"(p), "f"(mx), "f"(my), "f"(mz), "f"(mw) : "memory");
}

// ---------------- BN stats over columns ----------------
__global__ void k_stats() {
    int c = threadIdx.x;       // 512 threads, column per thread
    int base = blockIdx.x * 256;
    float s = 0.f, s2 = 0.f;
    for (int r = 0; r < 256; r++) {
        int row = base + r;
        if (row >= NN) break;
        float v = g_agg[(size_t)row * DD + c];
        s += v;
        s2 += v * v;
    }
    atomicAdd(&g_colsum[c], (double)s);
    atomicAdd(&g_colsq[c], (double)s2);
}

__global__ void k_finalize() {
    int c = threadIdx.x;
    if (c < DD) {
        double mu = g_colsum[c] / (double)NN;
        double var = g_colsq[c] / (double)NN - mu * mu;
        g_mu[c] = (float)mu;
        g_inv[c] = (float)(1.0 / sqrt(var + 1e-5));
    }
}

// ---------------- BN apply (+relu + vn pooling, or final output) ----------------
__global__ void k_bnapply(const int* __restrict__ batch, const float* __restrict__ ga,
                          const float* __restrict__ be, float* __restrict__ out, int last) {
    int c = threadIdx.x;
    int base = blockIdx.x * 64;
    float mu = g_mu[c], inv = g_inv[c], g = ga[c], b = be[c];
    if (last) {
        for (int r = 0; r < 64; r++) {
            int row = base + r;
            if (row >= NN) break;
            float v = g_agg[(size_t)row * DD + c];
            out[(size_t)row * DD + c] = (v - mu) * inv * g + b;
        }
        return;
    }
    int cur = -1;
    float acc = 0.f;
    for (int r = 0; r < 64; r++) {
        int row = base + r;
        if (row >= NN) break;
        float v = g_agg[(size_t)row * DD + c];
        v = (v - mu) * inv * g + b;
        v = fmaxf(v, 0.f);
        g_h[(size_t)row * DD + c] = v;
        int bg = batch[row];
        if (bg != cur) {
            if (cur >= 0) atomicAdd(&g_vnacc[cur * DD + c], acc);
            cur = bg;
            acc = 0.f;
        }
        acc += v;
    }
    if (cur >= 0) atomicAdd(&g_vnacc[cur * DD + c], acc);
}

// ---------------- virtual-node MLP ----------------
__global__ void k_vng1(const float* __restrict__ W1, const float* __restrict__ b1) {
    __shared__ float sh[2][DD];
    int r0 = blockIdx.x * 2;
    int tid = threadIdx.x;       // 256
#pragma unroll
    for (int i = 0; i < 4; i++) {
        int idx = tid + i * 256;
        int r = idx >> 9;
        int c = idx & 511;
        sh[r][c] = g_vn[(r0 + r) * DD + c] + g_vnacc[(r0 + r) * DD + c];
    }
    __syncthreads();
    float acc[2][4] = {{0.f, 0.f, 0.f, 0.f}, {0.f, 0.f, 0.f, 0.f}};
    for (int k = 0; k < DD; k++) {
        float s0 = sh[0][k], s1 = sh[1][k];
#pragma unroll
        for (int j = 0; j < 4; j++) {
            float w = W1[(size_t)k * 1024 + tid + j * 256];
            acc[0][j] += s0 * w;
            acc[1][j] += s1 * w;
        }
    }
#pragma unroll
    for (int r = 0; r < 2; r++)
#pragma unroll
        for (int j = 0; j < 4; j++) {
            int col = tid + j * 256;
            g_t[(r0 + r) * 1024 + col] = acc[r][j] + b1[col];
        }
}

__global__ void k_vnstats() {
    int c = threadIdx.x;   // 1024
    float s = 0.f, s2 = 0.f;
    for (int r = 0; r < GG; r++) {
        float v = g_t[r * 1024 + c];
        s += v; s2 += v * v;
    }
    float mu = s / (float)GG;
    float var = s2 / (float)GG - mu * mu;
    g_vmu[c] = mu;
    g_vinv[c] = rsqrtf(var + 1e-5f);
}

__global__ void k_vng2(const float* __restrict__ W2, const float* __restrict__ b2,
                       const float* __restrict__ mg, const float* __restrict__ mbb) {
    __shared__ float sh[2][2 * DD];
    int r0 = blockIdx.x * 2;
    int tid = threadIdx.x;       // 256
#pragma unroll
    for (int i = 0; i < 8; i++) {
        int idx = tid + i * 256;
        int r = idx >> 10;
        int c = idx & 1023;
        float v = g_t[(r0 + r) * 1024 + c];
        v = (v - g_vmu[c]) * g_vinv[c] * mg[c] + mbb[c];
        sh[r][c] = fmaxf(v, 0.f);
    }
    __syncthreads();
    float acc[2][2] = {{0.f, 0.f}, {0.f, 0.f}};
    for (int k = 0; k < 1024; k++) {
        float s0 = sh[0][k], s1 = sh[1][k];
#pragma unroll
        for (int j = 0; j < 2; j++) {
            float w = W2[(size_t)k * DD + tid + j * 256];
            acc[0][j] += s0 * w;
            acc[1][j] += s1 * w;
        }
    }
#pragma unroll
    for (int r = 0; r < 2; r++)
#pragma unroll
        for (int j = 0; j < 2; j++) {
            int col = tid + j * 256;
            g_vn[(r0 + r) * DD + col] = acc[r][j] + b2[col];
        }
}

// ---------------- launcher ----------------
extern "C" void kernel_launch(void* const* d_in, const int* in_sizes, int n_in,
                              void* d_out, int out_size) {
    const int*   x     = (const int*)d_in[0];
    const int*   nd    = (const int*)d_in[1];
    const int*   ei    = (const int*)d_in[2];
    const int*   batch = (const int*)d_in[3];
    const float* ea    = (const float*)d_in[4];
    const float* te    = (const float*)d_in[5];
    const float* ae    = (const float*)d_in[6];
    const float* de    = (const float*)d_in[7];
    const float* vnw   = (const float*)d_in[8];
    const float* lw    = (const float*)d_in[9];
    const float* lb    = (const float*)d_in[10];
    const float* cb    = (const float*)d_in[11];
    const float* ew    = (const float*)d_in[12];
    const float* ebi   = (const float*)d_in[13];
    const float* bng   = (const float*)d_in[14];
    const float* bnb   = (const float*)d_in[15];
    const float* mw1   = (const float*)d_in[16];
    const float* mb1   = (const float*)d_in[17];
    const float* mg    = (const float*)d_in[18];
    const float* mbb   = (const float*)d_in[19];
    const float* mw2   = (const float*)d_in[20];
    const float* mb2   = (const float*)d_in[21];
    float* out = (float*)d_out;

    static int smem_set = 0;
    if (!smem_set) {
        cudaFuncSetAttribute(k_gemm, cudaFuncAttributeMaxDynamicSharedMemorySize, SM_TOT);
        smem_set = 1;
    }

    k_init_deg<<<(NN + 255) / 256, 256>>>();
    k_deg<<<(EE + 255) / 256, 256>>>(ei);
    k_norm<<<(EE + 255) / 256, 256>>>(ei);
    k_embed<<<(NN * 128 + 255) / 256, 256>>>(x, nd, te, ae, de);
    k_vninit<<<(GG * DD + 255) / 256, 256>>>(vnw);

    for (int l = 0; l < LL; l++) {
        int last = (l == LL - 1) ? 1 : 0;
        k_zero<<<(GG * DD + 255) / 256, 256>>>();
        k_split_w<<<DD * DD / 4 / 256, 256>>>(lw + (size_t)l * DD * DD);
        k_split_a<<<(NN * 128 + 255) / 256, 256>>>(batch);
        k_gemm<<<dim3(DD / BN, NN2 / BM), 256, SM_TOT>>>(lb + l * DD, cb + l * DD);
        k_message<<<EE, 128>>>(ei, ea, ew + (size_t)l * 2 * DD, ebi + l * DD);
        k_stats<<<(NN + 255) / 256, 512>>>();
        k_finalize<<<1, 512>>>();
        k_bnapply<<<(NN + 63) / 64, 512>>>(batch, bng + l * DD, bnb + l * DD, out, last);
        if (!last) {
            k_vng1<<<GG / 2, 256>>>(mw1 + (size_t)l * DD * 2 * DD, mb1 + l * 2 * DD);
            k_vnstats<<<1, 1024>>>();
            k_vng2<<<GG / 2, 256>>>(mw2 + (size_t)l * 2 * DD * DD, mb2 + l * DD,
                                    mg + l * 2 * DD, mbb + l * 2 * DD);
        }
    }
    (void)in_sizes; (void)n_in; (void)out_size;
}